// round 3
// baseline (speedup 1.0000x reference)
#include <cuda_runtime.h>
#include <cuda_fp16.h>
#include <stdint.h>

// WindowAttention, GB300. B_=4096 windows, N=49, H=8, hd=32, q=k=v=x.
// Round 3: K/V MMA fragments hoisted out of the rq loop (loaded once per warp),
// fused (mask+bias)*log2e plane stored fp16 (3.7MB, L2-resident),
// vectorized x fill. 2 CTAs/SM (regs ~125).

#define NTOK 49
#define NPAD 64
#define NHEAD 8
#define HD 32
#define DIMC 256
#define XSTR 264   // half stride per row (528B: 16B-aligned, conflict-free ldmatrix)
#define FJ 56      // fused plane row width (padded cols)
#define FI 64      // fused plane rows (padded rows)

// fused[(w*8+h)*FI*FJ + i*FJ + j] = half((mask[w,i,j] + bias[rel[i,j],h]) * log2e)
__device__ __half g_fused[64 * NHEAD * FI * FJ];   // 3.67 MB

__global__ void precompute_fused(const float* __restrict__ bias_table,
                                 const float* __restrict__ mask,
                                 const int* __restrict__ rel) {
  const int w = blockIdx.x >> 3, h = blockIdx.x & 7;
  __half2* outp = reinterpret_cast<__half2*>(g_fused + (size_t)blockIdx.x * FI * FJ);
  for (int p = threadIdx.x; p < FI * FJ / 2; p += blockDim.x) {
    int idx = p * 2;
    int i = idx / FJ, j = idx - i * FJ;
    float v0 = -30000.f, v1 = -30000.f;
    if (i < NTOK && j < NTOK)
      v0 = (mask[(w * NTOK + i) * NTOK + j] +
            bias_table[rel[i * NTOK + j] * NHEAD + h]) * 1.4426950408889634f;
    if (i < NTOK && j + 1 < NTOK)
      v1 = (mask[(w * NTOK + i) * NTOK + j + 1] +
            bias_table[rel[i * NTOK + j + 1] * NHEAD + h]) * 1.4426950408889634f;
    outp[p] = __floats2half2_rn(v0, v1);
  }
}

__device__ __forceinline__ void mma16816(float* c, const uint32_t* a, uint32_t b0, uint32_t b1) {
  asm volatile(
      "mma.sync.aligned.m16n8k16.row.col.f32.f16.f16.f32 "
      "{%0,%1,%2,%3},{%4,%5,%6,%7},{%8,%9},{%0,%1,%2,%3};\n"
      : "+f"(c[0]), "+f"(c[1]), "+f"(c[2]), "+f"(c[3])
      : "r"(a[0]), "r"(a[1]), "r"(a[2]), "r"(a[3]), "r"(b0), "r"(b1));
}

__device__ __forceinline__ void ldsm_x4(uint32_t* r, uint32_t addr) {
  asm volatile("ldmatrix.sync.aligned.m8n8.x4.shared.b16 {%0,%1,%2,%3},[%4];\n"
               : "=r"(r[0]), "=r"(r[1]), "=r"(r[2]), "=r"(r[3]) : "r"(addr));
}
__device__ __forceinline__ void ldsm_x4_t(uint32_t* r, uint32_t addr) {
  asm volatile("ldmatrix.sync.aligned.m8n8.x4.trans.shared.b16 {%0,%1,%2,%3},[%4];\n"
               : "=r"(r[0]), "=r"(r[1]), "=r"(r[2]), "=r"(r[3]) : "r"(addr));
}

__device__ __forceinline__ uint32_t pack2f(float a, float b) {
  __half2 h = __floats2half2_rn(a, b);
  return *reinterpret_cast<uint32_t*>(&h);
}
__device__ __forceinline__ float ex2(float x) {
  float r;
  asm("ex2.approx.ftz.f32 %0, %1;\n" : "=f"(r) : "f"(x));
  return r;
}

__global__ void __launch_bounds__(256, 2)
winattn_kernel(const float* __restrict__ x, float* __restrict__ out) {
  __shared__ __half xh[NPAD * XSTR];   // 33792 B
  const int tid = threadIdx.x;
  const int b = blockIdx.x;
  const int w = b & 63;   // b = img*64 + w

  // ---- fill: x -> fp16 plane (float4 loads), zero pad rows ----
  {
    uint4* p = reinterpret_cast<uint4*>(xh + NTOK * XSTR);
    const int n128 = (NPAD - NTOK) * XSTR / 8;   // 495
    for (int i = tid; i < n128; i += 256) p[i] = make_uint4(0u, 0u, 0u, 0u);
  }
  {
    const float4* x4 = reinterpret_cast<const float4*>(x) + (size_t)b * NTOK * (DIMC / 4);
    for (int idx = tid; idx < NTOK * (DIMC / 4); idx += 256) {
      int r = idx >> 6, c4 = idx & 63;
      float4 v = x4[idx];
      __half2 lo = __floats2half2_rn(v.x, v.y);
      __half2 hi = __floats2half2_rn(v.z, v.w);
      *reinterpret_cast<__half2*>(xh + r * XSTR + c4 * 4) = lo;
      *reinterpret_cast<__half2*>(xh + r * XSTR + c4 * 4 + 2) = hi;
    }
  }
  __syncthreads();

  const int lane = tid & 31;
  const int g = lane >> 2, t = lane & 3;
  const int h = tid >> 5;                  // warp = head
  const int lr = lane & 7, lm = lane >> 3; // ldmatrix row-in-matrix / matrix id
  const uint32_t smbase = (uint32_t)__cvta_generic_to_shared(xh);
  const __half2* fb = reinterpret_cast<const __half2*>(g_fused) + (size_t)(w * NHEAD + h) * (FI * FJ / 2);
  float* outb = out + (size_t)b * NTOK * DIMC + h * HD;
  const float SL2E = 0.25503480f;          // 32^-0.5 * log2(e)

  // ---- hoisted K B-fragments (rq-invariant): 7 x ldmatrix.x4 ----
  uint32_t kf[7][4];
#pragma unroll
  for (int nt = 0; nt < 7; nt++) {
    uint32_t a = smbase + (((nt * 8 + lr) * XSTR + h * HD + lm * 8) << 1);
    ldsm_x4(kf[nt], a);
  }
  // ---- hoisted V B-fragments (rq-invariant): 8 x ldmatrix.x4.trans ----
  uint32_t vf[4][2][4];
#pragma unroll
  for (int kt = 0; kt < 4; kt++)
#pragma unroll
    for (int ntb = 0; ntb < 2; ntb++) {
      uint32_t a = smbase +
          (((kt * 16 + ((lm & 1) << 3) + lr) * XSTR + h * HD + (ntb * 2 + (lm >> 1)) * 8) << 1);
      ldsm_x4_t(vf[kt][ntb], a);
    }

#pragma unroll 1
  for (int rq = 0; rq < 4; rq++) {
    const int q0 = rq * 16;
    const int i0 = q0 + g, i1 = i0 + 8;

    // prefetch fused bias+mask rows (fp16, L2 hits; land during S MMAs)
    __half2 fA[7], fB[7];
#pragma unroll
    for (int nt = 0; nt < 7; nt++) {
      fA[nt] = fb[i0 * (FJ / 2) + nt * 4 + t];
      fB[nt] = fb[i1 * (FJ / 2) + nt * 4 + t];
    }

    // Q A-fragments: one ldmatrix.x4 per kt
    uint32_t qa[2][4];
#pragma unroll
    for (int kt = 0; kt < 2; kt++) {
      uint32_t a = smbase +
          (((q0 + ((lm & 1) << 3) + lr) * XSTR + h * HD + kt * 16 + ((lm >> 1) << 3)) << 1);
      ldsm_x4(qa[kt], a);
    }

    float sc[7][4];
#pragma unroll
    for (int i = 0; i < 7; i++)
#pragma unroll
      for (int k = 0; k < 4; k++) sc[i][k] = 0.f;

    // S = x @ x^T (fp16)
#pragma unroll
    for (int nt = 0; nt < 7; nt++) {
      mma16816(sc[nt], qa[0], kf[nt][0], kf[nt][1]);
      mma16816(sc[nt], qa[1], kf[nt][2], kf[nt][3]);
    }

    // softmax in log2 domain
    float mx0 = -1e30f, mx1 = -1e30f;
#pragma unroll
    for (int nt = 0; nt < 7; nt++) {
      float2 fa = __half22float2(fA[nt]);
      float2 fbv = __half22float2(fB[nt]);
      float s0 = fmaf(sc[nt][0], SL2E, fa.x);
      float s1 = fmaf(sc[nt][1], SL2E, fa.y);
      float s2 = fmaf(sc[nt][2], SL2E, fbv.x);
      float s3 = fmaf(sc[nt][3], SL2E, fbv.y);
      sc[nt][0] = s0; sc[nt][1] = s1; sc[nt][2] = s2; sc[nt][3] = s3;
      mx0 = fmaxf(mx0, fmaxf(s0, s1));
      mx1 = fmaxf(mx1, fmaxf(s2, s3));
    }
    mx0 = fmaxf(mx0, __shfl_xor_sync(0xffffffffu, mx0, 1));
    mx0 = fmaxf(mx0, __shfl_xor_sync(0xffffffffu, mx0, 2));
    mx1 = fmaxf(mx1, __shfl_xor_sync(0xffffffffu, mx1, 1));
    mx1 = fmaxf(mx1, __shfl_xor_sync(0xffffffffu, mx1, 2));
    float sum0 = 0.f, sum1 = 0.f;
#pragma unroll
    for (int nt = 0; nt < 7; nt++) {
      float e0 = ex2(sc[nt][0] - mx0);
      float e1 = ex2(sc[nt][1] - mx0);
      float e2 = ex2(sc[nt][2] - mx1);
      float e3 = ex2(sc[nt][3] - mx1);
      sc[nt][0] = e0; sc[nt][1] = e1; sc[nt][2] = e2; sc[nt][3] = e3;
      sum0 += e0 + e1; sum1 += e2 + e3;
    }
    sum0 += __shfl_xor_sync(0xffffffffu, sum0, 1);
    sum0 += __shfl_xor_sync(0xffffffffu, sum0, 2);
    sum1 += __shfl_xor_sync(0xffffffffu, sum1, 1);
    sum1 += __shfl_xor_sync(0xffffffffu, sum1, 2);
    const float rn0 = 1.f / sum0, rn1 = 1.f / sum1;

    // O = P @ V (hoisted V frags)
    float oc[4][4];
#pragma unroll
    for (int i = 0; i < 4; i++)
#pragma unroll
      for (int k = 0; k < 4; k++) oc[i][k] = 0.f;

    const float zz[4] = {0.f, 0.f, 0.f, 0.f};
#pragma unroll
    for (int kt = 0; kt < 4; kt++) {
      const float* sA = sc[2 * kt];
      const float* sB = (kt < 3) ? sc[2 * kt + 1] : zz;   // j>=56 tile: P = 0
      uint32_t pa[4];
      pa[0] = pack2f(sA[0] * rn0, sA[1] * rn0);
      pa[1] = pack2f(sA[2] * rn1, sA[3] * rn1);
      pa[2] = pack2f(sB[0] * rn0, sB[1] * rn0);
      pa[3] = pack2f(sB[2] * rn1, sB[3] * rn1);
#pragma unroll
      for (int ntb = 0; ntb < 2; ntb++) {
        mma16816(oc[ntb * 2 + 0], pa, vf[kt][ntb][0], vf[kt][ntb][1]);
        mma16816(oc[ntb * 2 + 1], pa, vf[kt][ntb][2], vf[kt][ntb][3]);
      }
    }

    // store valid rows
    if (i0 < NTOK) {
#pragma unroll
      for (int nt2 = 0; nt2 < 4; nt2++) {
        float2 v; v.x = oc[nt2][0]; v.y = oc[nt2][1];
        *reinterpret_cast<float2*>(outb + (size_t)i0 * DIMC + nt2 * 8 + t * 2) = v;
      }
    }
    if (i1 < NTOK) {
#pragma unroll
      for (int nt2 = 0; nt2 < 4; nt2++) {
        float2 v; v.x = oc[nt2][2]; v.y = oc[nt2][3];
        *reinterpret_cast<float2*>(outb + (size_t)i1 * DIMC + nt2 * 8 + t * 2) = v;
      }
    }
  }
}

extern "C" void kernel_launch(void* const* d_in, const int* in_sizes, int n_in,
                              void* d_out, int out_size) {
  (void)in_sizes; (void)n_in; (void)out_size;
  const float* x = (const float*)d_in[0];
  const float* bias_table = (const float*)d_in[1];
  const float* mask = (const float*)d_in[2];
  const int* rel = (const int*)d_in[3];
  float* out = (float*)d_out;

  precompute_fused<<<64 * NHEAD, 256>>>(bias_table, mask, rel);
  winattn_kernel<<<4096, 256>>>(x, out);
}

// round 4
// speedup vs baseline: 1.1768x; 1.1768x over previous
#include <cuda_runtime.h>
#include <cuda_fp16.h>
#include <stdint.h>

// WindowAttention, GB300. B_=4096 windows, N=49, H=8, hd=32, q=k=v=x.
// Round 4: single hoisted fragment set kf[8][4] (x rows 0..63 x 32 dims) serves as
//  - K B-operand directly,
//  - V B-operand via in-register movmatrix transpose (zero LDS),
// Q loaded per-rq (2 ldmatrix.x4). fp16 fused (mask+bias)*log2e plane in L2.
// 3 CTAs/SM (launch_bounds caps regs at 85).

#define NTOK 49
#define NPAD 64
#define NHEAD 8
#define HD 32
#define DIMC 256
#define XSTR 264   // half stride per row (528B, 16B-aligned, ldmatrix conflict-free)
#define FJ 56
#define FI 64

__device__ __half g_fused[64 * NHEAD * FI * FJ];   // 3.67 MB, L2-resident

__global__ void precompute_fused(const float* __restrict__ bias_table,
                                 const float* __restrict__ mask,
                                 const int* __restrict__ rel) {
  const int w = blockIdx.x >> 3, h = blockIdx.x & 7;
  __half2* outp = reinterpret_cast<__half2*>(g_fused + (size_t)blockIdx.x * FI * FJ);
  for (int p = threadIdx.x; p < FI * FJ / 2; p += blockDim.x) {
    int idx = p * 2;
    int i = idx / FJ, j = idx - i * FJ;
    float v0 = -30000.f, v1 = -30000.f;
    if (i < NTOK && j < NTOK)
      v0 = (mask[(w * NTOK + i) * NTOK + j] +
            bias_table[rel[i * NTOK + j] * NHEAD + h]) * 1.4426950408889634f;
    if (i < NTOK && j + 1 < NTOK)
      v1 = (mask[(w * NTOK + i) * NTOK + j + 1] +
            bias_table[rel[i * NTOK + j + 1] * NHEAD + h]) * 1.4426950408889634f;
    outp[p] = __floats2half2_rn(v0, v1);
  }
}

__device__ __forceinline__ void mma16816(float* c, const uint32_t* a, uint32_t b0, uint32_t b1) {
  asm volatile(
      "mma.sync.aligned.m16n8k16.row.col.f32.f16.f16.f32 "
      "{%0,%1,%2,%3},{%4,%5,%6,%7},{%8,%9},{%0,%1,%2,%3};\n"
      : "+f"(c[0]), "+f"(c[1]), "+f"(c[2]), "+f"(c[3])
      : "r"(a[0]), "r"(a[1]), "r"(a[2]), "r"(a[3]), "r"(b0), "r"(b1));
}

__device__ __forceinline__ void ldsm_x4(uint32_t* r, uint32_t addr) {
  asm volatile("ldmatrix.sync.aligned.m8n8.x4.shared.b16 {%0,%1,%2,%3},[%4];\n"
               : "=r"(r[0]), "=r"(r[1]), "=r"(r[2]), "=r"(r[3]) : "r"(addr));
}
__device__ __forceinline__ uint32_t movm_t(uint32_t a) {
  uint32_t d;
  asm volatile("movmatrix.sync.aligned.m8n8.trans.b16 %0, %1;\n" : "=r"(d) : "r"(a));
  return d;
}

__device__ __forceinline__ uint32_t pack2f(float a, float b) {
  __half2 h = __floats2half2_rn(a, b);
  return *reinterpret_cast<uint32_t*>(&h);
}
__device__ __forceinline__ float ex2(float x) {
  float r;
  asm("ex2.approx.ftz.f32 %0, %1;\n" : "=f"(r) : "f"(x));
  return r;
}

__global__ void __launch_bounds__(256, 3)
winattn_kernel(const float* __restrict__ x, float* __restrict__ out) {
  __shared__ __half xh[NPAD * XSTR];   // 33792 B -> 3 CTAs/SM
  const int tid = threadIdx.x;
  const int b = blockIdx.x;
  const int w = b & 63;

  // ---- fill: x -> fp16 plane (float4 loads), zero pad rows 49..63 ----
  {
    uint4* p = reinterpret_cast<uint4*>(xh + NTOK * XSTR);
    const int n128 = (NPAD - NTOK) * XSTR / 8;
    for (int i = tid; i < n128; i += 256) p[i] = make_uint4(0u, 0u, 0u, 0u);
  }
  {
    const float4* x4 = reinterpret_cast<const float4*>(x) + (size_t)b * NTOK * (DIMC / 4);
    for (int idx = tid; idx < NTOK * (DIMC / 4); idx += 256) {
      int r = idx >> 6, c4 = idx & 63;
      float4 v = x4[idx];
      *reinterpret_cast<__half2*>(xh + r * XSTR + c4 * 4) = __floats2half2_rn(v.x, v.y);
      *reinterpret_cast<__half2*>(xh + r * XSTR + c4 * 4 + 2) = __floats2half2_rn(v.z, v.w);
    }
  }
  __syncthreads();

  const int lane = tid & 31;
  const int g = lane >> 2, t = lane & 3;
  const int h = tid >> 5;                  // warp = head
  const int lr = lane & 7, lm = lane >> 3;
  const uint32_t smbase = (uint32_t)__cvta_generic_to_shared(xh);
  const __half2* fb =
      reinterpret_cast<const __half2*>(g_fused) + (size_t)(w * NHEAD + h) * (FI * FJ / 2);
  float* outb = out + (size_t)b * NTOK * DIMC + h * HD;
  const float SL2E = 0.25503480f;          // 32^-0.5 * log2(e)

  // ---- hoisted fragments kf[jb][c]: rows jb*8..jb*8+7, cols h*32 + c*8..c*8+7 ----
  // serves K (B-operand, non-trans layout) and V (via movmatrix transpose).
  uint32_t kf[8][4];
#pragma unroll
  for (int jb = 0; jb < 8; jb++) {
    uint32_t a = smbase + (((jb * 8 + lr) * XSTR + h * HD + lm * 8) << 1);
    ldsm_x4(kf[jb], a);
  }

#pragma unroll 1
  for (int rq = 0; rq < 4; rq++) {
    const int q0 = rq * 16;
    const int i0 = q0 + g, i1 = i0 + 8;

    // Q A-fragments (2 x ldmatrix.x4 per rq)
    uint32_t qa[2][4];
#pragma unroll
    for (int kt = 0; kt < 2; kt++) {
      uint32_t a = smbase +
          (((q0 + ((lm & 1) << 3) + lr) * XSTR + h * HD + kt * 16 + ((lm >> 1) << 3)) << 1);
      ldsm_x4(qa[kt], a);
    }

    float sc[7][4];
#pragma unroll
    for (int i = 0; i < 7; i++)
#pragma unroll
      for (int k = 0; k < 4; k++) sc[i][k] = 0.f;

    // S = x @ x^T (fp16), K frags from kf
#pragma unroll
    for (int nt = 0; nt < 7; nt++) {
      mma16816(sc[nt], qa[0], kf[nt][0], kf[nt][1]);
      mma16816(sc[nt], qa[1], kf[nt][2], kf[nt][3]);
    }

    // softmax (log2 domain); fused loads inline (L2 hits)
    float mx0 = -1e30f, mx1 = -1e30f;
#pragma unroll
    for (int nt = 0; nt < 7; nt++) {
      float2 fa = __half22float2(fb[i0 * (FJ / 2) + nt * 4 + t]);
      float2 fbv = __half22float2(fb[i1 * (FJ / 2) + nt * 4 + t]);
      float s0 = fmaf(sc[nt][0], SL2E, fa.x);
      float s1 = fmaf(sc[nt][1], SL2E, fa.y);
      float s2 = fmaf(sc[nt][2], SL2E, fbv.x);
      float s3 = fmaf(sc[nt][3], SL2E, fbv.y);
      sc[nt][0] = s0; sc[nt][1] = s1; sc[nt][2] = s2; sc[nt][3] = s3;
      mx0 = fmaxf(mx0, fmaxf(s0, s1));
      mx1 = fmaxf(mx1, fmaxf(s2, s3));
    }
    mx0 = fmaxf(mx0, __shfl_xor_sync(0xffffffffu, mx0, 1));
    mx0 = fmaxf(mx0, __shfl_xor_sync(0xffffffffu, mx0, 2));
    mx1 = fmaxf(mx1, __shfl_xor_sync(0xffffffffu, mx1, 1));
    mx1 = fmaxf(mx1, __shfl_xor_sync(0xffffffffu, mx1, 2));
    float sum0 = 0.f, sum1 = 0.f;
#pragma unroll
    for (int nt = 0; nt < 7; nt++) {
      float e0 = ex2(sc[nt][0] - mx0);
      float e1 = ex2(sc[nt][1] - mx0);
      float e2 = ex2(sc[nt][2] - mx1);
      float e3 = ex2(sc[nt][3] - mx1);
      sc[nt][0] = e0; sc[nt][1] = e1; sc[nt][2] = e2; sc[nt][3] = e3;
      sum0 += e0 + e1; sum1 += e2 + e3;
    }
    sum0 += __shfl_xor_sync(0xffffffffu, sum0, 1);
    sum0 += __shfl_xor_sync(0xffffffffu, sum0, 2);
    sum1 += __shfl_xor_sync(0xffffffffu, sum1, 1);
    sum1 += __shfl_xor_sync(0xffffffffu, sum1, 2);
    const float rn0 = 1.f / sum0, rn1 = 1.f / sum1;

    // O = P @ V; V frags derived from kf via movmatrix (kf[7] is the zero pad tile)
    float oc[4][4];
#pragma unroll
    for (int i = 0; i < 4; i++)
#pragma unroll
      for (int k = 0; k < 4; k++) oc[i][k] = 0.f;

    const float zz[4] = {0.f, 0.f, 0.f, 0.f};
#pragma unroll
    for (int kt = 0; kt < 4; kt++) {
      const float* sA = sc[2 * kt];
      const float* sB = (kt < 3) ? sc[2 * kt + 1] : zz;
      uint32_t pa[4];
      pa[0] = pack2f(sA[0] * rn0, sA[1] * rn0);
      pa[1] = pack2f(sA[2] * rn1, sA[3] * rn1);
      pa[2] = pack2f(sB[0] * rn0, sB[1] * rn0);
      pa[3] = pack2f(sB[2] * rn1, sB[3] * rn1);
#pragma unroll
      for (int c = 0; c < 4; c++) {
        uint32_t b0 = movm_t(kf[2 * kt][c]);
        uint32_t b1 = movm_t(kf[2 * kt + 1][c]);
        mma16816(oc[c], pa, b0, b1);
      }
    }

    // store valid rows
    if (i0 < NTOK) {
#pragma unroll
      for (int c = 0; c < 4; c++) {
        float2 v; v.x = oc[c][0]; v.y = oc[c][1];
        *reinterpret_cast<float2*>(outb + (size_t)i0 * DIMC + c * 8 + t * 2) = v;
      }
    }
    if (i1 < NTOK) {
#pragma unroll
      for (int c = 0; c < 4; c++) {
        float2 v; v.x = oc[c][2]; v.y = oc[c][3];
        *reinterpret_cast<float2*>(outb + (size_t)i1 * DIMC + c * 8 + t * 2) = v;
      }
    }
  }
}

extern "C" void kernel_launch(void* const* d_in, const int* in_sizes, int n_in,
                              void* d_out, int out_size) {
  (void)in_sizes; (void)n_in; (void)out_size;
  const float* x = (const float*)d_in[0];
  const float* bias_table = (const float*)d_in[1];
  const float* mask = (const float*)d_in[2];
  const int* rel = (const int*)d_in[3];
  float* out = (float*)d_out;

  precompute_fused<<<64 * NHEAD, 256>>>(bias_table, mask, rel);
  winattn_kernel<<<4096, 256>>>(x, out);
}

// round 5
// speedup vs baseline: 1.3749x; 1.1683x over previous
#include <cuda_runtime.h>
#include <cuda_fp16.h>
#include <stdint.h>

// WindowAttention, GB300. B_=4096 windows, N=49, H=8, hd=32, q=k=v=x.
// Round 5: round-2 structure (per-rq ldmatrix, minimal live regs) +
//  - fp16 softmax tail (ex2.approx.f16x2, unnormalized fp16 P into PV MMA,
//    fp32 1/sum applied on output accumulators),
//  - 64-reg cap -> 4 CTAs/SM.

#define NTOK 49
#define NPAD 64
#define NHEAD 8
#define HD 32
#define DIMC 256
#define XSTR 264   // half stride per row (528B, 16B-aligned, ldmatrix conflict-free)
#define FJ 56
#define FI 64

__device__ __half g_fused[64 * NHEAD * FI * FJ];   // 3.67 MB, L2-resident

__global__ void precompute_fused(const float* __restrict__ bias_table,
                                 const float* __restrict__ mask,
                                 const int* __restrict__ rel) {
  const int w = blockIdx.x >> 3, h = blockIdx.x & 7;
  __half2* outp = reinterpret_cast<__half2*>(g_fused + (size_t)blockIdx.x * FI * FJ);
  for (int p = threadIdx.x; p < FI * FJ / 2; p += blockDim.x) {
    int idx = p * 2;
    int i = idx / FJ, j = idx - i * FJ;
    float v0 = -30000.f, v1 = -30000.f;
    if (i < NTOK && j < NTOK)
      v0 = (mask[(w * NTOK + i) * NTOK + j] +
            bias_table[rel[i * NTOK + j] * NHEAD + h]) * 1.4426950408889634f;
    if (i < NTOK && j + 1 < NTOK)
      v1 = (mask[(w * NTOK + i) * NTOK + j + 1] +
            bias_table[rel[i * NTOK + j + 1] * NHEAD + h]) * 1.4426950408889634f;
    outp[p] = __floats2half2_rn(v0, v1);
  }
}

__device__ __forceinline__ void mma16816(float* c, const uint32_t* a, uint32_t b0, uint32_t b1) {
  asm volatile(
      "mma.sync.aligned.m16n8k16.row.col.f32.f16.f16.f32 "
      "{%0,%1,%2,%3},{%4,%5,%6,%7},{%8,%9},{%0,%1,%2,%3};\n"
      : "+f"(c[0]), "+f"(c[1]), "+f"(c[2]), "+f"(c[3])
      : "r"(a[0]), "r"(a[1]), "r"(a[2]), "r"(a[3]), "r"(b0), "r"(b1));
}

__device__ __forceinline__ void ldsm_x4(uint32_t* r, uint32_t addr) {
  asm volatile("ldmatrix.sync.aligned.m8n8.x4.shared.b16 {%0,%1,%2,%3},[%4];\n"
               : "=r"(r[0]), "=r"(r[1]), "=r"(r[2]), "=r"(r[3]) : "r"(addr));
}
__device__ __forceinline__ void ldsm_x4_t(uint32_t* r, uint32_t addr) {
  asm volatile("ldmatrix.sync.aligned.m8n8.x4.trans.shared.b16 {%0,%1,%2,%3},[%4];\n"
               : "=r"(r[0]), "=r"(r[1]), "=r"(r[2]), "=r"(r[3]) : "r"(addr));
}

__device__ __forceinline__ uint32_t h2ex2(uint32_t x) {
  uint32_t r;
  asm("ex2.approx.f16x2 %0, %1;\n" : "=r"(r) : "r"(x));
  return r;
}
__device__ __forceinline__ uint32_t packh2(float a, float b) {
  __half2 h = __floats2half2_rn(a, b);
  return *reinterpret_cast<uint32_t*>(&h);
}
__device__ __forceinline__ float2 h2f2(uint32_t x) {
  return __half22float2(*reinterpret_cast<__half2*>(&x));
}

__global__ void __launch_bounds__(256, 4)
winattn_kernel(const float* __restrict__ x, float* __restrict__ out) {
  __shared__ __half xh[NPAD * XSTR];   // 33792 B; 4 CTAs/SM = 135 KB
  const int tid = threadIdx.x;
  const int b = blockIdx.x;
  const int w = b & 63;

  // ---- fill: x -> fp16 plane (float4 loads), zero pad rows 49..63 ----
  {
    uint4* p = reinterpret_cast<uint4*>(xh + NTOK * XSTR);
    const int n128 = (NPAD - NTOK) * XSTR / 8;
    for (int i = tid; i < n128; i += 256) p[i] = make_uint4(0u, 0u, 0u, 0u);
  }
  {
    const float4* x4 = reinterpret_cast<const float4*>(x) + (size_t)b * NTOK * (DIMC / 4);
    for (int idx = tid; idx < NTOK * (DIMC / 4); idx += 256) {
      int r = idx >> 6, c4 = idx & 63;
      float4 v = x4[idx];
      *reinterpret_cast<__half2*>(xh + r * XSTR + c4 * 4) = __floats2half2_rn(v.x, v.y);
      *reinterpret_cast<__half2*>(xh + r * XSTR + c4 * 4 + 2) = __floats2half2_rn(v.z, v.w);
    }
  }
  __syncthreads();

  const int lane = tid & 31;
  const int g = lane >> 2, t = lane & 3;
  const int h = tid >> 5;                  // warp = head
  const int lr = lane & 7, lm = lane >> 3;
  const uint32_t smbase = (uint32_t)__cvta_generic_to_shared(xh);
  const __half2* fb =
      reinterpret_cast<const __half2*>(g_fused) + (size_t)(w * NHEAD + h) * (FI * FJ / 2);
  float* outb = out + (size_t)b * NTOK * DIMC + h * HD;
  const float SL2E = 0.25503480f;          // 32^-0.5 * log2(e)

#pragma unroll 1
  for (int rq = 0; rq < 4; rq++) {
    const int q0 = rq * 16;
    const int i0 = q0 + g, i1 = i0 + 8;

    // prefetch fused bias+mask rows (fp16, L2; land under the S MMAs)
    uint32_t fA[7], fB[7];
#pragma unroll
    for (int nt = 0; nt < 7; nt++) {
      fA[nt] = *reinterpret_cast<const uint32_t*>(fb + i0 * (FJ / 2) + nt * 4 + t);
      fB[nt] = *reinterpret_cast<const uint32_t*>(fb + i1 * (FJ / 2) + nt * 4 + t);
    }

    // Q A-fragments
    uint32_t qa[2][4];
#pragma unroll
    for (int kt = 0; kt < 2; kt++) {
      uint32_t a = smbase +
          (((q0 + ((lm & 1) << 3) + lr) * XSTR + h * HD + kt * 16 + ((lm >> 1) << 3)) << 1);
      ldsm_x4(qa[kt], a);
    }

    float sc[7][4];
#pragma unroll
    for (int i = 0; i < 7; i++)
#pragma unroll
      for (int k = 0; k < 4; k++) sc[i][k] = 0.f;

    // S = x @ x^T (fp16); K frags loaded per tile
#pragma unroll
    for (int nt = 0; nt < 7; nt++) {
      uint32_t kfr[4];
      uint32_t a = smbase + (((nt * 8 + lr) * XSTR + h * HD + lm * 8) << 1);
      ldsm_x4(kfr, a);
      mma16816(sc[nt], qa[0], kfr[0], kfr[1]);
      mma16816(sc[nt], qa[1], kfr[2], kfr[3]);
    }

    // logits (log2 domain) + row max
    float mx0 = -1e30f, mx1 = -1e30f;
#pragma unroll
    for (int nt = 0; nt < 7; nt++) {
      float2 fa = h2f2(fA[nt]);
      float2 fbv = h2f2(fB[nt]);
      float s0 = fmaf(sc[nt][0], SL2E, fa.x);
      float s1 = fmaf(sc[nt][1], SL2E, fa.y);
      float s2 = fmaf(sc[nt][2], SL2E, fbv.x);
      float s3 = fmaf(sc[nt][3], SL2E, fbv.y);
      sc[nt][0] = s0; sc[nt][1] = s1; sc[nt][2] = s2; sc[nt][3] = s3;
      mx0 = fmaxf(mx0, fmaxf(s0, s1));
      mx1 = fmaxf(mx1, fmaxf(s2, s3));
    }
    mx0 = fmaxf(mx0, __shfl_xor_sync(0xffffffffu, mx0, 1));
    mx0 = fmaxf(mx0, __shfl_xor_sync(0xffffffffu, mx0, 2));
    mx1 = fmaxf(mx1, __shfl_xor_sync(0xffffffffu, mx1, 1));
    mx1 = fmaxf(mx1, __shfl_xor_sync(0xffffffffu, mx1, 2));

    // exp2 in fp16x2: pA/pB hold UNNORMALIZED probabilities (<=1)
    uint32_t pA[7], pB[7];
    float sum0 = 0.f, sum1 = 0.f;
#pragma unroll
    for (int nt = 0; nt < 7; nt++) {
      pA[nt] = h2ex2(packh2(sc[nt][0] - mx0, sc[nt][1] - mx0));
      pB[nt] = h2ex2(packh2(sc[nt][2] - mx1, sc[nt][3] - mx1));
      float2 a = h2f2(pA[nt]);
      float2 c = h2f2(pB[nt]);
      sum0 += a.x + a.y;
      sum1 += c.x + c.y;
    }
    sum0 += __shfl_xor_sync(0xffffffffu, sum0, 1);
    sum0 += __shfl_xor_sync(0xffffffffu, sum0, 2);
    sum1 += __shfl_xor_sync(0xffffffffu, sum1, 1);
    sum1 += __shfl_xor_sync(0xffffffffu, sum1, 2);
    const float rn0 = 1.f / sum0, rn1 = 1.f / sum1;

    // O = P @ V (P fp16, unnormalized); V frags loaded per kt
    float oc[4][4];
#pragma unroll
    for (int i = 0; i < 4; i++)
#pragma unroll
      for (int k = 0; k < 4; k++) oc[i][k] = 0.f;

#pragma unroll
    for (int kt = 0; kt < 4; kt++) {
      uint32_t pa[4];
      pa[0] = pA[2 * kt];
      pa[1] = pB[2 * kt];
      pa[2] = (kt < 3) ? pA[2 * kt + 1] : 0u;   // tile 7: P = 0
      pa[3] = (kt < 3) ? pB[2 * kt + 1] : 0u;
#pragma unroll
      for (int ntb = 0; ntb < 2; ntb++) {
        uint32_t vfr[4];
        uint32_t a = smbase +
            (((kt * 16 + ((lm & 1) << 3) + lr) * XSTR + h * HD + (ntb * 2 + (lm >> 1)) * 8) << 1);
        ldsm_x4_t(vfr, a);
        mma16816(oc[ntb * 2 + 0], pa, vfr[0], vfr[1]);
        mma16816(oc[ntb * 2 + 1], pa, vfr[2], vfr[3]);
      }
    }

    // normalize in fp32 at store time
    if (i0 < NTOK) {
#pragma unroll
      for (int c = 0; c < 4; c++) {
        float2 v; v.x = oc[c][0] * rn0; v.y = oc[c][1] * rn0;
        *reinterpret_cast<float2*>(outb + (size_t)i0 * DIMC + c * 8 + t * 2) = v;
      }
    }
    if (i1 < NTOK) {
#pragma unroll
      for (int c = 0; c < 4; c++) {
        float2 v; v.x = oc[c][2] * rn1; v.y = oc[c][3] * rn1;
        *reinterpret_cast<float2*>(outb + (size_t)i1 * DIMC + c * 8 + t * 2) = v;
      }
    }
  }
}

extern "C" void kernel_launch(void* const* d_in, const int* in_sizes, int n_in,
                              void* d_out, int out_size) {
  (void)in_sizes; (void)n_in; (void)out_size;
  const float* x = (const float*)d_in[0];
  const float* bias_table = (const float*)d_in[1];
  const float* mask = (const float*)d_in[2];
  const int* rel = (const int*)d_in[3];
  float* out = (float*)d_out;

  precompute_fused<<<64 * NHEAD, 256>>>(bias_table, mask, rel);
  winattn_kernel<<<4096, 256>>>(x, out);
}

// round 6
// speedup vs baseline: 1.3817x; 1.0050x over previous
#include <cuda_runtime.h>
#include <cuda_fp16.h>
#include <stdint.h>

// WindowAttention, GB300. B_=4096 windows, N=49, H=8, hd=32, q=k=v=x.
// Round 6: fragment-major coalesced fused table (LDG.64/lane), Q aliased from
// diag K fragments (15 ldsm/rq), 512-thread CTAs (warp = head x rq-pair),
// fp16 softmax tail with fp32 normalization at store. 64-reg cap, 2 CTAs/SM.

#define NTOK 49
#define NPAD 64
#define NHEAD 8
#define HD 32
#define DIMC 256
#define XSTR 264   // half stride per row (528B, 16B-aligned, ldmatrix conflict-free)
#define RECS (4 * 7 * 32)   // uint2 records per (w,h): rq x nt x lane

// g_fused[(w*8+h)*RECS + (rq*7+nt)*32 + lane]:
//  .x = half2(L(i0,j0), L(i0,j0+1)), .y = half2(L(i1,j0), L(i1,j0+1))
//  i0=16rq+(lane>>2), i1=i0+8, j0=nt*8+(lane&3)*2,
//  L(i,j) = (mask[w,i,j] + bias_table[rel[i,j],h]) * log2e, -30000 if OOB.
__device__ uint2 g_fused[64 * NHEAD * RECS];   // 3.67 MB, L2-resident

__global__ void precompute_fused(const float* __restrict__ bias_table,
                                 const float* __restrict__ mask,
                                 const int* __restrict__ rel) {
  const int w = blockIdx.x >> 3, h = blockIdx.x & 7;
  __shared__ float sm_mask[NTOK * NTOK];
  __shared__ float sm_bias[169];
  __shared__ uint8_t sm_rel[NTOK * NTOK];
  for (int i = threadIdx.x; i < NTOK * NTOK; i += blockDim.x) {
    sm_mask[i] = mask[w * NTOK * NTOK + i];
    sm_rel[i] = (uint8_t)rel[i];
  }
  for (int i = threadIdx.x; i < 169; i += blockDim.x)
    sm_bias[i] = bias_table[i * NHEAD + h];
  __syncthreads();

  uint2* op = g_fused + (size_t)blockIdx.x * RECS;
  const float L2E = 1.4426950408889634f;
  for (int p = threadIdx.x; p < RECS; p += blockDim.x) {
    int rq = p / 224, rem = p - rq * 224;
    int nt = rem >> 5, lane = rem & 31;
    int g = lane >> 2, t = lane & 3;
    int i0 = rq * 16 + g, i1 = i0 + 8, j0 = nt * 8 + t * 2;
    float v[4];
#pragma unroll
    for (int q = 0; q < 4; q++) {
      int i = (q < 2) ? i0 : i1;
      int j = j0 + (q & 1);
      float val = -30000.f;
      if (i < NTOK && j < NTOK) {
        int ij = i * NTOK + j;
        val = (sm_mask[ij] + sm_bias[sm_rel[ij]]) * L2E;
      }
      v[q] = val;
    }
    uint2 r;
    __half2 a = __floats2half2_rn(v[0], v[1]);
    __half2 c = __floats2half2_rn(v[2], v[3]);
    r.x = *reinterpret_cast<uint32_t*>(&a);
    r.y = *reinterpret_cast<uint32_t*>(&c);
    op[p] = r;
  }
}

__device__ __forceinline__ void mma16816(float* c, const uint32_t* a, uint32_t b0, uint32_t b1) {
  asm volatile(
      "mma.sync.aligned.m16n8k16.row.col.f32.f16.f16.f32 "
      "{%0,%1,%2,%3},{%4,%5,%6,%7},{%8,%9},{%0,%1,%2,%3};\n"
      : "+f"(c[0]), "+f"(c[1]), "+f"(c[2]), "+f"(c[3])
      : "r"(a[0]), "r"(a[1]), "r"(a[2]), "r"(a[3]), "r"(b0), "r"(b1));
}

__device__ __forceinline__ void ldsm_x4(uint32_t* r, uint32_t addr) {
  asm volatile("ldmatrix.sync.aligned.m8n8.x4.shared.b16 {%0,%1,%2,%3},[%4];\n"
               : "=r"(r[0]), "=r"(r[1]), "=r"(r[2]), "=r"(r[3]) : "r"(addr));
}
__device__ __forceinline__ void ldsm_x4_t(uint32_t* r, uint32_t addr) {
  asm volatile("ldmatrix.sync.aligned.m8n8.x4.trans.shared.b16 {%0,%1,%2,%3},[%4];\n"
               : "=r"(r[0]), "=r"(r[1]), "=r"(r[2]), "=r"(r[3]) : "r"(addr));
}

__device__ __forceinline__ uint32_t h2ex2(uint32_t x) {
  uint32_t r;
  asm("ex2.approx.f16x2 %0, %1;\n" : "=r"(r) : "r"(x));
  return r;
}
__device__ __forceinline__ uint32_t packh2(float a, float b) {
  __half2 h = __floats2half2_rn(a, b);
  return *reinterpret_cast<uint32_t*>(&h);
}
__device__ __forceinline__ float2 h2f2(uint32_t x) {
  return __half22float2(*reinterpret_cast<__half2*>(&x));
}

__global__ void __launch_bounds__(512, 2)
winattn_kernel(const float* __restrict__ x, float* __restrict__ out) {
  __shared__ __half xh[NPAD * XSTR];   // 33792 B; 2 CTAs/SM
  const int tid = threadIdx.x;
  const int b = blockIdx.x;
  const int w = b & 63;

  // ---- fill: x -> fp16 plane (float4 loads), zero pad rows 49..63 ----
  {
    uint4* p = reinterpret_cast<uint4*>(xh + NTOK * XSTR);
    const int n128 = (NPAD - NTOK) * XSTR / 8;
    for (int i = tid; i < n128; i += 512) p[i] = make_uint4(0u, 0u, 0u, 0u);
  }
  {
    const float4* x4 = reinterpret_cast<const float4*>(x) + (size_t)b * NTOK * (DIMC / 4);
    for (int idx = tid; idx < NTOK * (DIMC / 4); idx += 512) {
      int r = idx >> 6, c4 = idx & 63;
      float4 v = x4[idx];
      *reinterpret_cast<__half2*>(xh + r * XSTR + c4 * 4) = __floats2half2_rn(v.x, v.y);
      *reinterpret_cast<__half2*>(xh + r * XSTR + c4 * 4 + 2) = __floats2half2_rn(v.z, v.w);
    }
  }
  __syncthreads();

  const int lane = tid & 31;
  const int t = lane & 3;
  const int warp = tid >> 5;
  const int h = warp & 7;
  const int rqh = warp >> 3;               // 0: rq {0,1}, 1: rq {2,3}
  const int lr = lane & 7, lm = lane >> 3;
  const uint32_t smbase = (uint32_t)__cvta_generic_to_shared(xh);
  const uint2* fptr = g_fused + (size_t)(w * NHEAD + h) * RECS;
  float* outb = out + (size_t)b * NTOK * DIMC + h * HD;
  const float SL2E = 0.25503480f;          // 32^-0.5 * log2(e)
  const int g = lane >> 2;

#pragma unroll 1
  for (int rr = 0; rr < 2; rr++) {
    const int rq = rqh * 2 + rr;
    const int q0 = rq << 4;
    const int i0 = q0 + g, i1 = i0 + 8;
    const int d0 = rq * 2, d1 = d0 + 1;

    // coalesced fused prefetch: 7 x LDG.64 (L2 hits; land under the S MMAs)
    uint2 fz[7];
#pragma unroll
    for (int nt = 0; nt < 7; nt++) fz[nt] = fptr[(rq * 7 + nt) * 32 + lane];

    // diag K tiles double as Q A-fragments (identical ldmatrix layout)
    uint32_t kq0[4], kq1[4];
    ldsm_x4(kq0, smbase + (((q0 + lr) * XSTR + h * HD + lm * 8) << 1));
    ldsm_x4(kq1, smbase + (((q0 + 8 + lr) * XSTR + h * HD + lm * 8) << 1));
    uint32_t qa0[4] = {kq0[0], kq1[0], kq0[1], kq1[1]};   // k 0..15
    uint32_t qa1[4] = {kq0[2], kq1[2], kq0[3], kq1[3]};   // k 16..31

    float sc[7][4];
#pragma unroll
    for (int i = 0; i < 7; i++)
#pragma unroll
      for (int k = 0; k < 4; k++) sc[i][k] = 0.f;

    // S = x @ x^T (fp16); diag tiles reuse kq0/kq1, others loaded
#pragma unroll
    for (int nt = 0; nt < 7; nt++) {
      uint32_t kb[4];
      if (nt == d0) {
        kb[0] = kq0[0]; kb[1] = kq0[1]; kb[2] = kq0[2]; kb[3] = kq0[3];
      } else if (nt == d1) {
        kb[0] = kq1[0]; kb[1] = kq1[1]; kb[2] = kq1[2]; kb[3] = kq1[3];
      } else {
        ldsm_x4(kb, smbase + (((nt * 8 + lr) * XSTR + h * HD + lm * 8) << 1));
      }
      mma16816(sc[nt], qa0, kb[0], kb[1]);
      mma16816(sc[nt], qa1, kb[2], kb[3]);
    }

    // logits (log2 domain) + row max
    float mx0 = -1e30f, mx1 = -1e30f;
#pragma unroll
    for (int nt = 0; nt < 7; nt++) {
      float2 fa = h2f2(fz[nt].x);
      float2 fbv = h2f2(fz[nt].y);
      float s0 = fmaf(sc[nt][0], SL2E, fa.x);
      float s1 = fmaf(sc[nt][1], SL2E, fa.y);
      float s2 = fmaf(sc[nt][2], SL2E, fbv.x);
      float s3 = fmaf(sc[nt][3], SL2E, fbv.y);
      sc[nt][0] = s0; sc[nt][1] = s1; sc[nt][2] = s2; sc[nt][3] = s3;
      mx0 = fmaxf(mx0, fmaxf(s0, s1));
      mx1 = fmaxf(mx1, fmaxf(s2, s3));
    }
    mx0 = fmaxf(mx0, __shfl_xor_sync(0xffffffffu, mx0, 1));
    mx0 = fmaxf(mx0, __shfl_xor_sync(0xffffffffu, mx0, 2));
    mx1 = fmaxf(mx1, __shfl_xor_sync(0xffffffffu, mx1, 1));
    mx1 = fmaxf(mx1, __shfl_xor_sync(0xffffffffu, mx1, 2));

    // exp2 in fp16x2: pA/pB hold UNNORMALIZED probabilities (<=1)
    uint32_t pA[7], pB[7];
    float sum0 = 0.f, sum1 = 0.f;
#pragma unroll
    for (int nt = 0; nt < 7; nt++) {
      pA[nt] = h2ex2(packh2(sc[nt][0] - mx0, sc[nt][1] - mx0));
      pB[nt] = h2ex2(packh2(sc[nt][2] - mx1, sc[nt][3] - mx1));
      float2 a = h2f2(pA[nt]);
      float2 c = h2f2(pB[nt]);
      sum0 += a.x + a.y;
      sum1 += c.x + c.y;
    }
    sum0 += __shfl_xor_sync(0xffffffffu, sum0, 1);
    sum0 += __shfl_xor_sync(0xffffffffu, sum0, 2);
    sum1 += __shfl_xor_sync(0xffffffffu, sum1, 1);
    sum1 += __shfl_xor_sync(0xffffffffu, sum1, 2);
    const float rn0 = 1.f / sum0, rn1 = 1.f / sum1;

    // O = P @ V (P fp16, unnormalized); V frags loaded per kt
    float oc[4][4];
#pragma unroll
    for (int i = 0; i < 4; i++)
#pragma unroll
      for (int k = 0; k < 4; k++) oc[i][k] = 0.f;

#pragma unroll
    for (int kt = 0; kt < 4; kt++) {
      uint32_t pa[4];
      pa[0] = pA[2 * kt];
      pa[1] = pB[2 * kt];
      pa[2] = (kt < 3) ? pA[2 * kt + 1] : 0u;   // tile 7: P = 0
      pa[3] = (kt < 3) ? pB[2 * kt + 1] : 0u;
#pragma unroll
      for (int ntb = 0; ntb < 2; ntb++) {
        uint32_t vfr[4];
        uint32_t a = smbase +
            (((kt * 16 + ((lm & 1) << 3) + lr) * XSTR + h * HD + (ntb * 2 + (lm >> 1)) * 8) << 1);
        ldsm_x4_t(vfr, a);
        mma16816(oc[ntb * 2 + 0], pa, vfr[0], vfr[1]);
        mma16816(oc[ntb * 2 + 1], pa, vfr[2], vfr[3]);
      }
    }

    // normalize in fp32 at store time
    if (i0 < NTOK) {
#pragma unroll
      for (int c = 0; c < 4; c++) {
        float2 v; v.x = oc[c][0] * rn0; v.y = oc[c][1] * rn0;
        *reinterpret_cast<float2*>(outb + (size_t)i0 * DIMC + c * 8 + t * 2) = v;
      }
    }
    if (i1 < NTOK) {
#pragma unroll
      for (int c = 0; c < 4; c++) {
        float2 v; v.x = oc[c][2] * rn1; v.y = oc[c][3] * rn1;
        *reinterpret_cast<float2*>(outb + (size_t)i1 * DIMC + c * 8 + t * 2) = v;
      }
    }
  }
}

extern "C" void kernel_launch(void* const* d_in, const int* in_sizes, int n_in,
                              void* d_out, int out_size) {
  (void)in_sizes; (void)n_in; (void)out_size;
  const float* x = (const float*)d_in[0];
  const float* bias_table = (const float*)d_in[1];
  const float* mask = (const float*)d_in[2];
  const int* rel = (const int*)d_in[3];
  float* out = (float*)d_out;

  precompute_fused<<<64 * NHEAD, 256>>>(bias_table, mask, rel);
  winattn_kernel<<<4096, 512>>>(x, out);
}